// round 2
// baseline (speedup 1.0000x reference)
#include <cuda_runtime.h>
#include <math.h>

// Problem constants
#define BT     8192      // B*T tokens
#define KDIM   4096      // N*C flattened
#define NS     4         // streams
#define CDIM   1024      // embed
#define NOUT   24        // 4 pre + 4 post + 16 res
#define EPSV   1e-6f

// K1 tiling
#define TM       32      // tokens per block
#define KC       128     // k-chunk
#define WPITCH   132     // padded weight row pitch (conflict-free)
#define NT1      128     // threads in K1
#define GP       28      // gate staging pitch

// Gate scratch: per token [0..3]=h_pre, [4..7]=h_post, [8..23]=h_res (row-major n*4+m)
__device__ float g_gates[(size_t)BT * NOUT];

// ---------------------------------------------------------------------------
// K1: per-token sumsq + 24 dot products (tiled GEMM) + gate math (fused)
// Thread layout: tid = ks + 8*og + 32*tg   (ks: k-split, og: 6-output group,
// tg: 8-token group). Each thread accumulates 8 tokens x 6 outputs over its
// 1/8 stride-8 slice of k; shuffle-reduce over ks at the end.
// ---------------------------------------------------------------------------
__global__ void __launch_bounds__(NT1)
k1_gates(const float* __restrict__ stream,
         const float* __restrict__ w_pre,
         const float* __restrict__ w_post,
         const float* __restrict__ w_res,
         const float* __restrict__ b_pre,
         const float* __restrict__ b_post,
         const float* __restrict__ b_res,
         const float* __restrict__ a_pre,
         const float* __restrict__ a_post,
         const float* __restrict__ a_res)
{
    extern __shared__ float sm[];
    float* Ssm = sm;                    // TM * KC floats
    float* Wsm = sm + TM * KC;          // NOUT * WPITCH floats
    float* Gsm = sm;                    // aliased over Ssm after main loop (TM*GP)

    const int tid = threadIdx.x;
    const int ks  = tid & 7;
    const int og  = (tid >> 3) & 3;
    const int tg  = tid >> 5;
    const int tok0 = blockIdx.x * TM;

    float acc[8][6];
    float ssA[8];
#pragma unroll
    for (int j = 0; j < 8; ++j) {
        ssA[j] = 0.f;
#pragma unroll
        for (int r = 0; r < 6; ++r) acc[j][r] = 0.f;
    }

    for (int chunk = 0; chunk < KDIM / KC; ++chunk) {
        __syncthreads();   // previous chunk's compute done before restage
        // ---- stage stream tile: TM x KC (1024 float4, 8 per thread) ----
#pragma unroll
        for (int q = 0; q < 8; ++q) {
            int f   = tid + NT1 * q;       // 0..1023 float4 index
            int row = f >> 5;              // token row 0..31
            int c4  = f & 31;              // float4 col 0..31
            float4 v = *(const float4*)(stream + (size_t)(tok0 + row) * KDIM
                                        + chunk * KC + c4 * 4);
            *(float4*)(Ssm + row * KC + c4 * 4) = v;
        }
        // ---- stage weight tile: NOUT x KC (768 float4, 6 per thread) ----
#pragma unroll
        for (int q = 0; q < 6; ++q) {
            int f   = tid + NT1 * q;       // 0..767
            int row = f >> 5;              // 0..23
            int c4  = f & 31;
            const float* src = (row < 4)  ? (w_pre  + (size_t)row * KDIM)
                             : (row < 8)  ? (w_post + (size_t)(row - 4) * KDIM)
                                          : (w_res  + (size_t)(row - 8) * KDIM);
            float4 v = *(const float4*)(src + chunk * KC + c4 * 4);
            *(float4*)(Wsm + row * WPITCH + c4 * 4) = v;
        }
        __syncthreads();
        // ---- compute ----
#pragma unroll
        for (int i = 0; i < KC / 8; ++i) {
            const int kk = ks + 8 * i;
            float sv[8], wv[6];
#pragma unroll
            for (int j = 0; j < 8; ++j) sv[j] = Ssm[(tg * 8 + j) * KC + kk];
#pragma unroll
            for (int r = 0; r < 6; ++r) wv[r] = Wsm[(og * 6 + r) * WPITCH + kk];
#pragma unroll
            for (int j = 0; j < 8; ++j)
#pragma unroll
                for (int r = 0; r < 6; ++r) acc[j][r] += sv[j] * wv[r];
            if (og == 0) {
#pragma unroll
                for (int j = 0; j < 8; ++j) ssA[j] += sv[j] * sv[j];
            }
        }
    }

    // ---- shuffle-reduce over ks (lanes differing in low 3 bits) ----
#pragma unroll
    for (int j = 0; j < 8; ++j) {
#pragma unroll
        for (int r = 0; r < 6; ++r) {
            acc[j][r] += __shfl_xor_sync(0xffffffffu, acc[j][r], 1);
            acc[j][r] += __shfl_xor_sync(0xffffffffu, acc[j][r], 2);
            acc[j][r] += __shfl_xor_sync(0xffffffffu, acc[j][r], 4);
        }
        ssA[j] += __shfl_xor_sync(0xffffffffu, ssA[j], 1);
        ssA[j] += __shfl_xor_sync(0xffffffffu, ssA[j], 2);
        ssA[j] += __shfl_xor_sync(0xffffffffu, ssA[j], 4);
    }

    __syncthreads();   // Ssm reads finished; safe to alias Gsm
    if (ks == 0) {
#pragma unroll
        for (int j = 0; j < 8; ++j) {
#pragma unroll
            for (int r = 0; r < 6; ++r)
                Gsm[(tg * 8 + j) * GP + og * 6 + r] = acc[j][r];
            if (og == 0) Gsm[(tg * 8 + j) * GP + 24] = ssA[j];
        }
    }
    __syncthreads();

    // ---- gate math: one thread per token ----
    if (tid < TM) {
        const float* G = Gsm + tid * GP;
        const float inv = rsqrtf(G[24] * (1.0f / KDIM) + EPSV);
        const float ap = a_pre[0], aq = a_post[0], ar = a_res[0];
        const int t = tok0 + tid;
        float* gout = g_gates + (size_t)t * NOUT;

#pragma unroll
        for (int n = 0; n < 4; ++n) {
            float xpre  = ap * G[n] * inv + b_pre[n];
            float xpost = aq * G[4 + n] * inv + b_post[n];
            gout[n]     = 1.0f / (1.0f + expf(-xpre));
            gout[4 + n] = 2.0f / (1.0f + expf(-xpost));
        }
        // Sinkhorn on 4x4 (row-major n*4+m)
        float e[16];
        float mx = -1e30f;
#pragma unroll
        for (int j = 0; j < 16; ++j) {
            float l = ar * G[8 + j] * inv + b_res[j];
            e[j] = l;
            mx = fmaxf(mx, l);
        }
#pragma unroll
        for (int j = 0; j < 16; ++j) e[j] = expf(e[j] - mx);
#pragma unroll
        for (int it = 0; it < 5; ++it) {
#pragma unroll
            for (int n = 0; n < 4; ++n) {   // row normalize (sum over m)
                float s = e[n*4] + e[n*4+1] + e[n*4+2] + e[n*4+3] + 1e-6f;
                float rcp = 1.0f / s;
                e[n*4] *= rcp; e[n*4+1] *= rcp; e[n*4+2] *= rcp; e[n*4+3] *= rcp;
            }
#pragma unroll
            for (int m = 0; m < 4; ++m) {   // col normalize (sum over n)
                float s = e[m] + e[4+m] + e[8+m] + e[12+m] + 1e-6f;
                float rcp = 1.0f / s;
                e[m] *= rcp; e[4+m] *= rcp; e[8+m] *= rcp; e[12+m] *= rcp;
            }
        }
#pragma unroll
        for (int j = 0; j < 16; ++j) gout[8 + j] = e[j];
    }
}

// ---------------------------------------------------------------------------
// K2: streaming combine. One block per token, 256 threads, float4 per thread.
// x_in[c]       = sum_n h_pre[n] * s[n][c]
// updated[n][c] = sum_m h_res[n][m] * s[m][c] + h_post[n] * out[c]
// ---------------------------------------------------------------------------
__global__ void __launch_bounds__(256)
k2_combine(const float* __restrict__ stream,
           const float* __restrict__ outv,
           float* __restrict__ xin,
           float* __restrict__ upd)
{
    __shared__ float g[NOUT];
    const int t = blockIdx.x;
    const int tid = threadIdx.x;
    if (tid < NOUT) g[tid] = g_gates[(size_t)t * NOUT + tid];
    __syncthreads();

    const float4* sp = (const float4*)(stream + (size_t)t * KDIM);
    float4 s0 = sp[tid];
    float4 s1 = sp[256 + tid];
    float4 s2 = sp[512 + tid];
    float4 s3 = sp[768 + tid];
    float4 ov = ((const float4*)(outv + (size_t)t * CDIM))[tid];

    // x_in
    float4 x;
    x.x = g[0]*s0.x + g[1]*s1.x + g[2]*s2.x + g[3]*s3.x;
    x.y = g[0]*s0.y + g[1]*s1.y + g[2]*s2.y + g[3]*s3.y;
    x.z = g[0]*s0.z + g[1]*s1.z + g[2]*s2.z + g[3]*s3.z;
    x.w = g[0]*s0.w + g[1]*s1.w + g[2]*s2.w + g[3]*s3.w;
    ((float4*)(xin + (size_t)t * CDIM))[tid] = x;

    float4* up = (float4*)(upd + (size_t)t * KDIM);
#pragma unroll
    for (int n = 0; n < 4; ++n) {
        const float h0 = g[8 + n*4 + 0];
        const float h1 = g[8 + n*4 + 1];
        const float h2 = g[8 + n*4 + 2];
        const float h3 = g[8 + n*4 + 3];
        const float hp = g[4 + n];
        float4 u;
        u.x = h0*s0.x + h1*s1.x + h2*s2.x + h3*s3.x + hp*ov.x;
        u.y = h0*s0.y + h1*s1.y + h2*s2.y + h3*s3.y + hp*ov.y;
        u.z = h0*s0.z + h1*s1.z + h2*s2.z + h3*s3.z + hp*ov.z;
        u.w = h0*s0.w + h1*s1.w + h2*s2.w + h3*s3.w + hp*ov.w;
        up[n * 256 + tid] = u;
    }
}

// ---------------------------------------------------------------------------
extern "C" void kernel_launch(void* const* d_in, const int* in_sizes, int n_in,
                              void* d_out, int out_size)
{
    const float* stream = (const float*)d_in[0];
    const float* outv   = (const float*)d_in[1];
    const float* w_pre  = (const float*)d_in[2];
    const float* w_post = (const float*)d_in[3];
    const float* w_res  = (const float*)d_in[4];
    const float* b_pre  = (const float*)d_in[5];
    const float* b_post = (const float*)d_in[6];
    const float* b_res  = (const float*)d_in[7];
    const float* a_pre  = (const float*)d_in[8];
    const float* a_post = (const float*)d_in[9];
    const float* a_res  = (const float*)d_in[10];

    float* xin = (float*)d_out;                      // (B,T,C)
    float* upd = xin + (size_t)BT * CDIM;            // (B,T,N,C)

    size_t smem = (size_t)(TM * KC + NOUT * WPITCH) * sizeof(float);
    k1_gates<<<BT / TM, NT1, smem>>>(stream, w_pre, w_post, w_res,
                                     b_pre, b_post, b_res,
                                     a_pre, a_post, a_res);
    k2_combine<<<BT, 256>>>(stream, outv, xin, upd);
}

// round 4
// speedup vs baseline: 1.1170x; 1.1170x over previous
#include <cuda_runtime.h>
#include <math.h>

// Problem constants
#define BT     8192      // B*T tokens
#define KDIM   4096      // N*C flattened
#define CDIM   1024      // embed
#define NOUT   24        // 4 pre + 4 post + 16 res
#define EPSV   1e-6f

// K1 tiling
#define TM       32      // tokens per block
#define KC       128     // k-chunk
#define SPITCH   128     // stream tile pitch (floats)
#define WPITCH   132     // weight tile pitch (floats, 16B-aligned, 2-phase banks)
#define NT1      256     // threads in K1
#define GP       28      // gate staging pitch

// Gate scratch: per token [0..3]=h_pre, [4..7]=h_post, [8..23]=h_res (n*4+m)
__device__ float g_gates[(size_t)BT * NOUT];

// packed f32x2 FMA: acc = a*b + acc  (two fp32 lanes per instruction)
__device__ __forceinline__ void ffma2(unsigned long long& acc,
                                      unsigned long long a,
                                      unsigned long long b)
{
    asm("fma.rn.f32x2 %0, %1, %2, %0;" : "+l"(acc) : "l"(a), "l"(b));
}
__device__ __forceinline__ float pk_lo(unsigned long long v) {
    return __uint_as_float((unsigned)(v & 0xffffffffull));
}
__device__ __forceinline__ float pk_hi(unsigned long long v) {
    return __uint_as_float((unsigned)(v >> 32));
}

// ---------------------------------------------------------------------------
// K1: per-token sumsq + 24 dot products + gate math (fused), f32x2 inner loop.
// tid = ks(0..7) + 8*og(0..3) + 32*warp(0..7).
// Each thread: 4 tokens (warp*4+j) x 6 outputs (og*6+r), k split 8-way in
// pairs: k = 2*ks + 16*i. Shuffle-reduce over ks (lane bits 0..2).
// ---------------------------------------------------------------------------
__global__ void __launch_bounds__(NT1)
k1_gates(const float* __restrict__ stream,
         const float* __restrict__ w_pre,
         const float* __restrict__ w_post,
         const float* __restrict__ w_res,
         const float* __restrict__ b_pre,
         const float* __restrict__ b_post,
         const float* __restrict__ b_res,
         const float* __restrict__ a_pre,
         const float* __restrict__ a_post,
         const float* __restrict__ a_res)
{
    extern __shared__ float sm[];
    float* Ssm = sm;                       // TM * SPITCH floats
    float* Wsm = sm + TM * SPITCH;         // NOUT * WPITCH floats
    float* Gsm = sm;                       // aliased over Ssm after main loop

    const int tid  = threadIdx.x;
    const int ks   = tid & 7;
    const int og   = (tid >> 3) & 3;
    const int warp = tid >> 5;
    const int tok0 = blockIdx.x * TM;

    unsigned long long acc[4][6];
    unsigned long long ss2[4];
#pragma unroll
    for (int j = 0; j < 4; ++j) {
        ss2[j] = 0ull;
#pragma unroll
        for (int r = 0; r < 6; ++r) acc[j][r] = 0ull;
    }

    for (int chunk = 0; chunk < KDIM / KC; ++chunk) {
        __syncthreads();   // previous chunk's compute done before restage
        // ---- stage stream tile: TM x KC (1024 float4, 4 per thread) ----
#pragma unroll
        for (int q = 0; q < 4; ++q) {
            int f   = tid + NT1 * q;       // 0..1023
            int row = f >> 5;
            int c4  = f & 31;
            float4 v = *(const float4*)(stream + (size_t)(tok0 + row) * KDIM
                                        + chunk * KC + c4 * 4);
            *(float4*)(Ssm + row * SPITCH + c4 * 4) = v;
        }
        // ---- stage weight tile: NOUT x KC (768 float4, 3 per thread) ----
#pragma unroll
        for (int q = 0; q < 3; ++q) {
            int f   = tid + NT1 * q;       // 0..767
            int row = f >> 5;              // 0..23
            int c4  = f & 31;
            const float* src = (row < 4)  ? (w_pre  + (size_t)row * KDIM)
                             : (row < 8)  ? (w_post + (size_t)(row - 4) * KDIM)
                                          : (w_res  + (size_t)(row - 8) * KDIM);
            float4 v = *(const float4*)(src + chunk * KC + c4 * 4);
            *(float4*)(Wsm + row * WPITCH + c4 * 4) = v;
        }
        __syncthreads();
        // ---- compute: 8 iters cover KC=128 in pairs ----
#pragma unroll
        for (int i = 0; i < 8; ++i) {
            const int kk = 2 * ks + 16 * i;
            unsigned long long sv[4], wv[6];
#pragma unroll
            for (int j = 0; j < 4; ++j)
                sv[j] = *(const unsigned long long*)(Ssm + (warp * 4 + j) * SPITCH + kk);
#pragma unroll
            for (int r = 0; r < 6; ++r)
                wv[r] = *(const unsigned long long*)(Wsm + (og * 6 + r) * WPITCH + kk);
#pragma unroll
            for (int j = 0; j < 4; ++j)
#pragma unroll
                for (int r = 0; r < 6; ++r) ffma2(acc[j][r], sv[j], wv[r]);
            if (og == 0) {
#pragma unroll
                for (int j = 0; j < 4; ++j) ffma2(ss2[j], sv[j], sv[j]);
            }
        }
    }

    // ---- reduce packed halves, then shuffle over ks (lane bits 0..2) ----
    float accf[4][6], ssf[4];
#pragma unroll
    for (int j = 0; j < 4; ++j) {
        ssf[j] = pk_lo(ss2[j]) + pk_hi(ss2[j]);
#pragma unroll
        for (int r = 0; r < 6; ++r) accf[j][r] = pk_lo(acc[j][r]) + pk_hi(acc[j][r]);
    }
#pragma unroll
    for (int j = 0; j < 4; ++j) {
#pragma unroll
        for (int r = 0; r < 6; ++r) {
            accf[j][r] += __shfl_xor_sync(0xffffffffu, accf[j][r], 1);
            accf[j][r] += __shfl_xor_sync(0xffffffffu, accf[j][r], 2);
            accf[j][r] += __shfl_xor_sync(0xffffffffu, accf[j][r], 4);
        }
        ssf[j] += __shfl_xor_sync(0xffffffffu, ssf[j], 1);
        ssf[j] += __shfl_xor_sync(0xffffffffu, ssf[j], 2);
        ssf[j] += __shfl_xor_sync(0xffffffffu, ssf[j], 4);
    }

    __syncthreads();   // Ssm reads finished; safe to alias Gsm
    if (ks == 0) {
#pragma unroll
        for (int j = 0; j < 4; ++j) {
#pragma unroll
            for (int r = 0; r < 6; ++r)
                Gsm[(warp * 4 + j) * GP + og * 6 + r] = accf[j][r];
            if (og == 0) Gsm[(warp * 4 + j) * GP + 24] = ssf[j];
        }
    }
    __syncthreads();

    // ---- gate math: one thread per token ----
    if (tid < TM) {
        const float* G = Gsm + tid * GP;
        const float inv = rsqrtf(G[24] * (1.0f / KDIM) + EPSV);
        const float ap = a_pre[0], aq = a_post[0], ar = a_res[0];
        const int t = tok0 + tid;
        float* gout = g_gates + (size_t)t * NOUT;

#pragma unroll
        for (int n = 0; n < 4; ++n) {
            float xpre  = ap * G[n] * inv + b_pre[n];
            float xpost = aq * G[4 + n] * inv + b_post[n];
            gout[n]     = 1.0f / (1.0f + expf(-xpre));
            gout[4 + n] = 2.0f / (1.0f + expf(-xpost));
        }
        // Sinkhorn on 4x4 (row-major n*4+m)
        float e[16];
        float mx = -1e30f;
#pragma unroll
        for (int j = 0; j < 16; ++j) {
            float l = ar * G[8 + j] * inv + b_res[j];
            e[j] = l;
            mx = fmaxf(mx, l);
        }
#pragma unroll
        for (int j = 0; j < 16; ++j) e[j] = expf(e[j] - mx);
#pragma unroll
        for (int it = 0; it < 5; ++it) {
#pragma unroll
            for (int n = 0; n < 4; ++n) {   // row normalize (sum over m)
                float s = e[n*4] + e[n*4+1] + e[n*4+2] + e[n*4+3] + 1e-6f;
                float rcp = 1.0f / s;
                e[n*4] *= rcp; e[n*4+1] *= rcp; e[n*4+2] *= rcp; e[n*4+3] *= rcp;
            }
#pragma unroll
            for (int m = 0; m < 4; ++m) {   // col normalize (sum over n)
                float s = e[m] + e[4+m] + e[8+m] + e[12+m] + 1e-6f;
                float rcp = 1.0f / s;
                e[m] *= rcp; e[4+m] *= rcp; e[8+m] *= rcp; e[12+m] *= rcp;
            }
        }
#pragma unroll
        for (int j = 0; j < 16; ++j) gout[8 + j] = e[j];
    }
}

// ---------------------------------------------------------------------------
// K2: streaming combine. One block per token, 256 threads, float4 per thread.
// (Measured at DRAM roofline: 72.5% DRAM, 5.93 TB/s — unchanged.)
// ---------------------------------------------------------------------------
__global__ void __launch_bounds__(256)
k2_combine(const float* __restrict__ stream,
           const float* __restrict__ outv,
           float* __restrict__ xin,
           float* __restrict__ upd)
{
    __shared__ float g[NOUT];
    const int t = blockIdx.x;
    const int tid = threadIdx.x;
    if (tid < NOUT) g[tid] = g_gates[(size_t)t * NOUT + tid];
    __syncthreads();

    const float4* sp = (const float4*)(stream + (size_t)t * KDIM);
    float4 s0 = sp[tid];
    float4 s1 = sp[256 + tid];
    float4 s2 = sp[512 + tid];
    float4 s3 = sp[768 + tid];
    float4 ov = ((const float4*)(outv + (size_t)t * CDIM))[tid];

    float4 x;
    x.x = g[0]*s0.x + g[1]*s1.x + g[2]*s2.x + g[3]*s3.x;
    x.y = g[0]*s0.y + g[1]*s1.y + g[2]*s2.y + g[3]*s3.y;
    x.z = g[0]*s0.z + g[1]*s1.z + g[2]*s2.z + g[3]*s3.z;
    x.w = g[0]*s0.w + g[1]*s1.w + g[2]*s2.w + g[3]*s3.w;
    ((float4*)(xin + (size_t)t * CDIM))[tid] = x;

    float4* up = (float4*)(upd + (size_t)t * KDIM);
#pragma unroll
    for (int n = 0; n < 4; ++n) {
        const float h0 = g[8 + n*4 + 0];
        const float h1 = g[8 + n*4 + 1];
        const float h2 = g[8 + n*4 + 2];
        const float h3 = g[8 + n*4 + 3];
        const float hp = g[4 + n];
        float4 u;
        u.x = h0*s0.x + h1*s1.x + h2*s2.x + h3*s3.x + hp*ov.x;
        u.y = h0*s0.y + h1*s1.y + h2*s2.y + h3*s3.y + hp*ov.y;
        u.z = h0*s0.z + h1*s1.z + h2*s2.z + h3*s3.z + hp*ov.z;
        u.w = h0*s0.w + h1*s1.w + h2*s2.w + h3*s3.w + hp*ov.w;
        up[n * 256 + tid] = u;
    }
}

// ---------------------------------------------------------------------------
extern "C" void kernel_launch(void* const* d_in, const int* in_sizes, int n_in,
                              void* d_out, int out_size)
{
    const float* stream = (const float*)d_in[0];
    const float* outv   = (const float*)d_in[1];
    const float* w_pre  = (const float*)d_in[2];
    const float* w_post = (const float*)d_in[3];
    const float* w_res  = (const float*)d_in[4];
    const float* b_pre  = (const float*)d_in[5];
    const float* b_post = (const float*)d_in[6];
    const float* b_res  = (const float*)d_in[7];
    const float* a_pre  = (const float*)d_in[8];
    const float* a_post = (const float*)d_in[9];
    const float* a_res  = (const float*)d_in[10];

    float* xin = (float*)d_out;                      // (B,T,C)
    float* upd = xin + (size_t)BT * CDIM;            // (B,T,N,C)

    size_t smem = (size_t)(TM * SPITCH + NOUT * WPITCH) * sizeof(float);
    k1_gates<<<BT / TM, NT1, smem>>>(stream, w_pre, w_post, w_res,
                                     b_pre, b_post, b_res,
                                     a_pre, a_post, a_res);
    k2_combine<<<BT, 256>>>(stream, outv, xin, upd);
}

// round 6
// speedup vs baseline: 1.1818x; 1.0580x over previous
#include <cuda_runtime.h>
#include <math.h>

// Problem constants
#define BT     8192      // B*T tokens
#define KDIM   4096      // N*C flattened
#define CDIM   1024      // embed
#define NOUT   24        // 4 pre + 4 post + 16 res
#define EPSV   1e-6f

// K1 tiling
#define TM     32        // tokens per block
#define NT1    256       // threads (8 warps)
#define KC     256       // k-chunk (floats); warp w owns 32 cols of each chunk
#define NCH    (KDIM / KC)   // 16 chunks
#define PITCH  260       // stream tile pitch (floats); 16B-aligned rows, spread banks
#define RSTRIDE 26       // reduction slot stride (24 outputs + sumsq + pad)

// Gate scratch: per token [0..3]=h_pre, [4..7]=h_post, [8..23]=h_res (n*4+m)
__device__ float g_gates[(size_t)BT * NOUT];
// Packed weights: rows 0-3 w_pre, 4-7 w_post, 8-23 w_res; row-major [24][4096]
__device__ float g_w[(size_t)NOUT * KDIM];

// packed f32x2 FMA: acc = a*b + acc
__device__ __forceinline__ void ffma2(unsigned long long& acc,
                                      unsigned long long a,
                                      unsigned long long b)
{
    asm("fma.rn.f32x2 %0, %1, %2, %0;" : "+l"(acc) : "l"(a), "l"(b));
}
__device__ __forceinline__ float pk_lo(unsigned long long v) {
    return __uint_as_float((unsigned)(v & 0xffffffffull));
}
__device__ __forceinline__ float pk_hi(unsigned long long v) {
    return __uint_as_float((unsigned)(v >> 32));
}

// ---------------------------------------------------------------------------
// K0: pack the 24 weight rows into one contiguous __device__ array (runs once
// per launch; ~0.8MB traffic, negligible).
// ---------------------------------------------------------------------------
__global__ void k0_pack_w(const float* __restrict__ wp,
                          const float* __restrict__ wq,
                          const float* __restrict__ wr)
{
    const int row = blockIdx.x;
    const float* src = (row < 4) ? (wp + (size_t)row * KDIM)
                     : (row < 8) ? (wq + (size_t)(row - 4) * KDIM)
                                 : (wr + (size_t)(row - 8) * KDIM);
    float4* dst = (float4*)(g_w + (size_t)row * KDIM);
    const float4* s4 = (const float4*)src;
    for (int i = threadIdx.x; i < KDIM / 4; i += blockDim.x)
        dst[i] = s4[i];
}

// ---------------------------------------------------------------------------
// K1: gates. k split ACROSS warps (each weight element read once per block,
// straight from global/L2 — no smem weight re-reads). Stream tile staged in
// smem per chunk. Lane = tk(16 tokens) + 16*oh(2 output halves of 12).
// Thread accumulates tokens {tk, tk+16} x outputs {oh*12..oh*12+11}, packed
// f32x2 over k-pairs. Cross-warp reduction in smem, then fused gate math.
// ---------------------------------------------------------------------------
__global__ void __launch_bounds__(NT1, 2)
k1_gates(const float* __restrict__ stream,
         const float* __restrict__ b_pre,
         const float* __restrict__ b_post,
         const float* __restrict__ b_res,
         const float* __restrict__ a_pre,
         const float* __restrict__ a_post,
         const float* __restrict__ a_res)
{
    extern __shared__ float sm[];          // TM * PITCH floats (33280 B)

    const int tid  = threadIdx.x;
    const int lane = tid & 31;
    const int w    = tid >> 5;             // warp 0..7 -> k-slice owner
    const int tk   = lane & 15;
    const int oh   = lane >> 4;            // output half: rows oh*12..oh*12+11
    const int tA   = tk;
    const int tB   = tk + 16;
    const int tok0 = blockIdx.x * TM;

    unsigned long long accA[12], accB[12], ssA = 0ull, ssB = 0ull;
#pragma unroll
    for (int rr = 0; rr < 12; ++rr) { accA[rr] = 0ull; accB[rr] = 0ull; }

    for (int c = 0; c < NCH; ++c) {
        __syncthreads();   // prior chunk fully consumed
        // ---- stage stream tile: TM x KC = 2048 float4, 8 per thread ----
#pragma unroll
        for (int i = 0; i < 8; ++i) {
            int f   = tid + NT1 * i;       // 0..2047
            int row = f >> 6;              // 0..31
            int c4  = f & 63;              // 0..63
            float4 v = *(const float4*)(stream + (size_t)(tok0 + row) * KDIM
                                        + c * KC + c4 * 4);
            *(float4*)(sm + row * PITCH + c4 * 4) = v;
        }
        __syncthreads();

        // warp's k-slice within chunk: [w*32, w*32+32)
        const float* wb = g_w + (size_t)(oh * 12) * KDIM + c * KC + w * 32;
        const float* sA = sm + tA * PITCH + w * 32;
        const float* sB = sm + tB * PITCH + w * 32;

#pragma unroll
        for (int q = 0; q < 8; ++q) {      // 8 quads of 4 floats
            ulonglong2 a = *(const ulonglong2*)(sA + 4 * q);
            ulonglong2 b = *(const ulonglong2*)(sB + 4 * q);
#pragma unroll
            for (int rr = 0; rr < 12; ++rr) {
                ulonglong2 wv = *(const ulonglong2*)(wb + (size_t)rr * KDIM + 4 * q);
                ffma2(accA[rr], wv.x, a.x);
                ffma2(accA[rr], wv.y, a.y);
                ffma2(accB[rr], wv.x, b.x);
                ffma2(accB[rr], wv.y, b.y);
            }
            if (oh == 0) {
                ffma2(ssA, a.x, a.x); ffma2(ssA, a.y, a.y);
                ffma2(ssB, b.x, b.x); ffma2(ssB, b.y, b.y);
            }
        }
    }

    // ---- unpack ----
    float rA[12], rB[12];
#pragma unroll
    for (int rr = 0; rr < 12; ++rr) {
        rA[rr] = pk_lo(accA[rr]) + pk_hi(accA[rr]);
        rB[rr] = pk_lo(accB[rr]) + pk_hi(accB[rr]);
    }
    const float fssA = pk_lo(ssA) + pk_hi(ssA);
    const float fssB = pk_lo(ssB) + pk_hi(ssB);

    __syncthreads();   // stream tile no longer needed; alias reduction buffer
    // red[w][token][RSTRIDE]: 8*32*26 = 6656 floats
    float* red = sm;
#pragma unroll
    for (int rr = 0; rr < 12; ++rr) {
        red[(w * TM + tA) * RSTRIDE + oh * 12 + rr] = rA[rr];
        red[(w * TM + tB) * RSTRIDE + oh * 12 + rr] = rB[rr];
    }
    if (oh == 0) {
        red[(w * TM + tA) * RSTRIDE + 24] = fssA;
        red[(w * TM + tB) * RSTRIDE + 24] = fssB;
    }
    __syncthreads();

    // ---- sum over 8 warps: 32 tokens x 25 values = 800 sums ----
    float* Gsm = sm + 8 * TM * RSTRIDE;    // 832 floats, total 7488 < 8320
    for (int idx = tid; idx < TM * 25; idx += NT1) {
        int t = idx / 25;
        int v = idx - t * 25;
        float s = 0.f;
#pragma unroll
        for (int ww = 0; ww < 8; ++ww)
            s += red[(ww * TM + t) * RSTRIDE + v];
        Gsm[t * RSTRIDE + v] = s;
    }
    __syncthreads();

    // ---- gate math: one thread per token ----
    if (tid < TM) {
        const float* G = Gsm + tid * RSTRIDE;
        const float inv = rsqrtf(G[24] * (1.0f / KDIM) + EPSV);
        const float ap = a_pre[0], aq = a_post[0], ar = a_res[0];
        const int t = tok0 + tid;
        float* gout = g_gates + (size_t)t * NOUT;

#pragma unroll
        for (int n = 0; n < 4; ++n) {
            float xpre  = ap * G[n] * inv + b_pre[n];
            float xpost = aq * G[4 + n] * inv + b_post[n];
            gout[n]     = 1.0f / (1.0f + expf(-xpre));
            gout[4 + n] = 2.0f / (1.0f + expf(-xpost));
        }
        // Sinkhorn on 4x4 (row-major n*4+m)
        float e[16];
        float mx = -1e30f;
#pragma unroll
        for (int j = 0; j < 16; ++j) {
            float l = ar * G[8 + j] * inv + b_res[j];
            e[j] = l;
            mx = fmaxf(mx, l);
        }
#pragma unroll
        for (int j = 0; j < 16; ++j) e[j] = expf(e[j] - mx);
#pragma unroll
        for (int it = 0; it < 5; ++it) {
#pragma unroll
            for (int n = 0; n < 4; ++n) {   // row normalize (sum over m)
                float s = e[n*4] + e[n*4+1] + e[n*4+2] + e[n*4+3] + 1e-6f;
                float rcp = 1.0f / s;
                e[n*4] *= rcp; e[n*4+1] *= rcp; e[n*4+2] *= rcp; e[n*4+3] *= rcp;
            }
#pragma unroll
            for (int m = 0; m < 4; ++m) {   // col normalize (sum over n)
                float s = e[m] + e[4+m] + e[8+m] + e[12+m] + 1e-6f;
                float rcp = 1.0f / s;
                e[m] *= rcp; e[4+m] *= rcp; e[8+m] *= rcp; e[12+m] *= rcp;
            }
        }
#pragma unroll
        for (int j = 0; j < 16; ++j) gout[8 + j] = e[j];
    }
}

// ---------------------------------------------------------------------------
// K2: streaming combine (measured at DRAM roofline — unchanged).
// ---------------------------------------------------------------------------
__global__ void __launch_bounds__(256)
k2_combine(const float* __restrict__ stream,
           const float* __restrict__ outv,
           float* __restrict__ xin,
           float* __restrict__ upd)
{
    __shared__ float g[NOUT];
    const int t = blockIdx.x;
    const int tid = threadIdx.x;
    if (tid < NOUT) g[tid] = g_gates[(size_t)t * NOUT + tid];
    __syncthreads();

    const float4* sp = (const float4*)(stream + (size_t)t * KDIM);
    float4 s0 = sp[tid];
    float4 s1 = sp[256 + tid];
    float4 s2 = sp[512 + tid];
    float4 s3 = sp[768 + tid];
    float4 ov = ((const float4*)(outv + (size_t)t * CDIM))[tid];

    float4 x;
    x.x = g[0]*s0.x + g[1]*s1.x + g[2]*s2.x + g[3]*s3.x;
    x.y = g[0]*s0.y + g[1]*s1.y + g[2]*s2.y + g[3]*s3.y;
    x.z = g[0]*s0.z + g[1]*s1.z + g[2]*s2.z + g[3]*s3.z;
    x.w = g[0]*s0.w + g[1]*s1.w + g[2]*s2.w + g[3]*s3.w;
    ((float4*)(xin + (size_t)t * CDIM))[tid] = x;

    float4* up = (float4*)(upd + (size_t)t * KDIM);
#pragma unroll
    for (int n = 0; n < 4; ++n) {
        const float h0 = g[8 + n*4 + 0];
        const float h1 = g[8 + n*4 + 1];
        const float h2 = g[8 + n*4 + 2];
        const float h3 = g[8 + n*4 + 3];
        const float hp = g[4 + n];
        float4 u;
        u.x = h0*s0.x + h1*s1.x + h2*s2.x + h3*s3.x + hp*ov.x;
        u.y = h0*s0.y + h1*s1.y + h2*s2.y + h3*s3.y + hp*ov.y;
        u.z = h0*s0.z + h1*s1.z + h2*s2.z + h3*s3.z + hp*ov.z;
        u.w = h0*s0.w + h1*s1.w + h2*s2.w + h3*s3.w + hp*ov.w;
        up[n * 256 + tid] = u;
    }
}

// ---------------------------------------------------------------------------
extern "C" void kernel_launch(void* const* d_in, const int* in_sizes, int n_in,
                              void* d_out, int out_size)
{
    const float* stream = (const float*)d_in[0];
    const float* outv   = (const float*)d_in[1];
    const float* w_pre  = (const float*)d_in[2];
    const float* w_post = (const float*)d_in[3];
    const float* w_res  = (const float*)d_in[4];
    const float* b_pre  = (const float*)d_in[5];
    const float* b_post = (const float*)d_in[6];
    const float* b_res  = (const float*)d_in[7];
    const float* a_pre  = (const float*)d_in[8];
    const float* a_post = (const float*)d_in[9];
    const float* a_res  = (const float*)d_in[10];

    float* xin = (float*)d_out;                      // (B,T,C)
    float* upd = xin + (size_t)BT * CDIM;            // (B,T,N,C)

    k0_pack_w<<<NOUT, 256>>>(w_pre, w_post, w_res);

    size_t smem = (size_t)(TM * PITCH) * sizeof(float);  // 33280 B
    k1_gates<<<BT / TM, NT1, smem>>>(stream,
                                     b_pre, b_post, b_res,
                                     a_pre, a_post, a_res);
    k2_combine<<<BT, 256>>>(stream, outv, xin, upd);
}

// round 7
// speedup vs baseline: 1.6779x; 1.4198x over previous
#include <cuda_runtime.h>
#include <math.h>

// Problem constants
#define BT     8192      // B*T tokens
#define KDIM   4096      // N*C flattened
#define CDIM   1024      // embed
#define NOUT   24        // 4 pre + 4 post + 16 res
#define EPSV   1e-6f

// K1 tiling
#define TM     32        // tokens per block
#define NT1    256       // threads (8 warps)
#define KC     128       // k-chunk (floats); warp w owns cols [16w,16w+16)
#define NCH    (KDIM / KC)   // 32 chunks
#define AP     132       // A tile pitch (floats): bank stride 4, conflict-free frags
#define WP     132       // W tile pitch
#define RSTRIDE 26

// Gate scratch: per token [0..3]=h_pre, [4..7]=h_post, [8..23]=h_res (n*4+m)
__device__ float g_gates[(size_t)BT * NOUT];

__device__ __forceinline__ unsigned f2tf32(float x) {
    unsigned u;
    asm("cvt.rna.tf32.f32 %0, %1;" : "=r"(u) : "f"(x));
    return u;
}

__device__ __forceinline__ void mma_tf32(float c[4], const unsigned a[4],
                                         const unsigned b[2]) {
    asm volatile(
        "mma.sync.aligned.m16n8k8.row.col.f32.tf32.tf32.f32 "
        "{%0,%1,%2,%3}, {%4,%5,%6,%7}, {%8,%9}, {%0,%1,%2,%3};"
        : "+f"(c[0]), "+f"(c[1]), "+f"(c[2]), "+f"(c[3])
        : "r"(a[0]), "r"(a[1]), "r"(a[2]), "r"(a[3]), "r"(b[0]), "r"(b[1]));
}

// ---------------------------------------------------------------------------
// K1: gate GEMM on tensor cores (tf32 mma.sync) + sumsq + gate math, fused.
// Per block: D[32 tok x 24 out] = S[32 x 4096] @ W^T, k split across 8 warps
// (warp w: cols 16w..16w+15 of each 128-chunk). Cross-warp smem reduction.
// ---------------------------------------------------------------------------
__global__ void __launch_bounds__(NT1, 2)
k1_gates(const float* __restrict__ stream,
         const float* __restrict__ w_pre,
         const float* __restrict__ w_post,
         const float* __restrict__ w_res,
         const float* __restrict__ b_pre,
         const float* __restrict__ b_post,
         const float* __restrict__ b_res,
         const float* __restrict__ a_pre,
         const float* __restrict__ a_post,
         const float* __restrict__ a_res)
{
    // region layout (floats):
    //   main phase: Asm = sm[0 .. 4224), Wsm = sm[4224 .. 7392)
    //   end phase:  red = sm[0 .. 6656), ssb = sm[6656 .. 7712), G = sm[7712 ..)
    __shared__ float sm[8544];
    float* Asm = sm;
    float* Wsm = sm + TM * AP;          // 4224

    const int tid  = threadIdx.x;
    const int lane = tid & 31;
    const int w    = tid >> 5;          // warp id = k-slice owner
    const int gid  = lane >> 2;         // mma group id (0..7)
    const int tig  = lane & 3;          // thread-in-group (0..3)
    const int tok0 = blockIdx.x * TM;

    float c[2][3][4];                   // [m-tile][n-tile][frag]
#pragma unroll
    for (int mt = 0; mt < 2; ++mt)
#pragma unroll
        for (int nt = 0; nt < 3; ++nt)
#pragma unroll
            for (int q = 0; q < 4; ++q) c[mt][nt][q] = 0.f;
    float ss[4] = {0.f, 0.f, 0.f, 0.f};    // sumsq for tokens w+8i

    for (int ch = 0; ch < NCH; ++ch) {
        __syncthreads();
        // ---- stage A: 32 x 128 fp32 -> tf32; accumulate sumsq (fp32) ----
#pragma unroll
        for (int i = 0; i < 4; ++i) {
            int row = w + 8 * i;                 // exact: (tid+256i)>>5
            float4 v = *(const float4*)(stream + (size_t)(tok0 + row) * KDIM
                                        + ch * KC + lane * 4);
            ss[i] += v.x * v.x + v.y * v.y + v.z * v.z + v.w * v.w;
            unsigned* d = (unsigned*)(Asm + row * AP + lane * 4);
            d[0] = f2tf32(v.x); d[1] = f2tf32(v.y);
            d[2] = f2tf32(v.z); d[3] = f2tf32(v.w);
        }
        // ---- stage W: 24 x 128 fp32 -> tf32 (row->source select, warp-uniform) ----
#pragma unroll
        for (int i = 0; i < 3; ++i) {
            int row = w + 8 * i;                 // 0..23
            const float* src = (row < 4)  ? (w_pre  + (size_t)row * KDIM)
                             : (row < 8)  ? (w_post + (size_t)(row - 4) * KDIM)
                                          : (w_res  + (size_t)(row - 8) * KDIM);
            float4 v = *(const float4*)(src + ch * KC + lane * 4);
            unsigned* d = (unsigned*)(Wsm + row * WP + lane * 4);
            d[0] = f2tf32(v.x); d[1] = f2tf32(v.y);
            d[2] = f2tf32(v.z); d[3] = f2tf32(v.w);
        }
        __syncthreads();

        // ---- compute: warp w covers cols [16w, 16w+16) = 2 k-steps ----
#pragma unroll
        for (int s = 0; s < 2; ++s) {
            const int kk = w * 16 + 8 * s;
            unsigned a[2][4], b[3][2];
#pragma unroll
            for (int mt = 0; mt < 2; ++mt) {
                const unsigned* A0 = (const unsigned*)(Asm + (mt * 16 + gid) * AP + kk + tig);
                a[mt][0] = A0[0];
                a[mt][2] = A0[4];
                a[mt][1] = A0[8 * AP];
                a[mt][3] = A0[8 * AP + 4];
            }
#pragma unroll
            for (int nt = 0; nt < 3; ++nt) {
                const unsigned* B0 = (const unsigned*)(Wsm + (nt * 8 + gid) * WP + kk + tig);
                b[nt][0] = B0[0];
                b[nt][1] = B0[4];
            }
#pragma unroll
            for (int mt = 0; mt < 2; ++mt)
#pragma unroll
                for (int nt = 0; nt < 3; ++nt)
                    mma_tf32(c[mt][nt], a[mt], b[nt]);
        }
    }

    __syncthreads();   // main-phase smem dead; alias end-phase buffers
    float* red = sm;                    // [8 warps][32 tok][26]
    float* ssb = sm + 6656;             // [32 tok][33]
    float* G   = sm + 7712;             // [32 tok][26]

    // store C fragments: c0:(gid, 2tig) c1:(gid, 2tig+1) c2:(gid+8,..) c3
#pragma unroll
    for (int mt = 0; mt < 2; ++mt)
#pragma unroll
        for (int nt = 0; nt < 3; ++nt) {
            int t0 = mt * 16 + gid, o0 = nt * 8 + 2 * tig;
            red[(w * TM + t0)     * RSTRIDE + o0]     = c[mt][nt][0];
            red[(w * TM + t0)     * RSTRIDE + o0 + 1] = c[mt][nt][1];
            red[(w * TM + t0 + 8) * RSTRIDE + o0]     = c[mt][nt][2];
            red[(w * TM + t0 + 8) * RSTRIDE + o0 + 1] = c[mt][nt][3];
        }
#pragma unroll
    for (int i = 0; i < 4; ++i)
        ssb[(w + 8 * i) * 33 + lane] = ss[i];
    __syncthreads();

    // sum over warps: 32 tokens x 24 outputs
    for (int idx = tid; idx < TM * NOUT; idx += NT1) {
        int t = idx / NOUT, v = idx - t * NOUT;
        float s = 0.f;
#pragma unroll
        for (int ww = 0; ww < 8; ++ww)
            s += red[(ww * TM + t) * RSTRIDE + v];
        G[t * RSTRIDE + v] = s;
    }
    if (tid < TM) {
        float s = 0.f;
#pragma unroll
        for (int l = 0; l < 32; ++l) s += ssb[tid * 33 + l];
        G[tid * RSTRIDE + 24] = s;
    }
    __syncthreads();

    // ---- gate math: one thread per token ----
    if (tid < TM) {
        const float* Gt = G + tid * RSTRIDE;
        const float inv = rsqrtf(Gt[24] * (1.0f / KDIM) + EPSV);
        const float ap = a_pre[0], aq = a_post[0], ar = a_res[0];
        const int t = tok0 + tid;
        float* gout = g_gates + (size_t)t * NOUT;

#pragma unroll
        for (int n = 0; n < 4; ++n) {
            float xpre  = ap * Gt[n] * inv + b_pre[n];
            float xpost = aq * Gt[4 + n] * inv + b_post[n];
            gout[n]     = 1.0f / (1.0f + expf(-xpre));
            gout[4 + n] = 2.0f / (1.0f + expf(-xpost));
        }
        // Sinkhorn on 4x4 (row-major n*4+m)
        float e[16];
        float mx = -1e30f;
#pragma unroll
        for (int j = 0; j < 16; ++j) {
            float l = ar * Gt[8 + j] * inv + b_res[j];
            e[j] = l;
            mx = fmaxf(mx, l);
        }
#pragma unroll
        for (int j = 0; j < 16; ++j) e[j] = expf(e[j] - mx);
#pragma unroll
        for (int it = 0; it < 5; ++it) {
#pragma unroll
            for (int n = 0; n < 4; ++n) {
                float s = e[n*4] + e[n*4+1] + e[n*4+2] + e[n*4+3] + 1e-6f;
                float rcp = 1.0f / s;
                e[n*4] *= rcp; e[n*4+1] *= rcp; e[n*4+2] *= rcp; e[n*4+3] *= rcp;
            }
#pragma unroll
            for (int m = 0; m < 4; ++m) {
                float s = e[m] + e[4+m] + e[8+m] + e[12+m] + 1e-6f;
                float rcp = 1.0f / s;
                e[m] *= rcp; e[4+m] *= rcp; e[8+m] *= rcp; e[12+m] *= rcp;
            }
        }
#pragma unroll
        for (int j = 0; j < 16; ++j) gout[8 + j] = e[j];
    }
}

// ---------------------------------------------------------------------------
// K2: streaming combine (measured at DRAM roofline — unchanged).
// ---------------------------------------------------------------------------
__global__ void __launch_bounds__(256)
k2_combine(const float* __restrict__ stream,
           const float* __restrict__ outv,
           float* __restrict__ xin,
           float* __restrict__ upd)
{
    __shared__ float g[NOUT];
    const int t = blockIdx.x;
    const int tid = threadIdx.x;
    if (tid < NOUT) g[tid] = g_gates[(size_t)t * NOUT + tid];
    __syncthreads();

    const float4* sp = (const float4*)(stream + (size_t)t * KDIM);
    float4 s0 = sp[tid];
    float4 s1 = sp[256 + tid];
    float4 s2 = sp[512 + tid];
    float4 s3 = sp[768 + tid];
    float4 ov = ((const float4*)(outv + (size_t)t * CDIM))[tid];

    float4 x;
    x.x = g[0]*s0.x + g[1]*s1.x + g[2]*s2.x + g[3]*s3.x;
    x.y = g[0]*s0.y + g[1]*s1.y + g[2]*s2.y + g[3]*s3.y;
    x.z = g[0]*s0.z + g[1]*s1.z + g[2]*s2.z + g[3]*s3.z;
    x.w = g[0]*s0.w + g[1]*s1.w + g[2]*s2.w + g[3]*s3.w;
    ((float4*)(xin + (size_t)t * CDIM))[tid] = x;

    float4* up = (float4*)(upd + (size_t)t * KDIM);
#pragma unroll
    for (int n = 0; n < 4; ++n) {
        const float h0 = g[8 + n*4 + 0];
        const float h1 = g[8 + n*4 + 1];
        const float h2 = g[8 + n*4 + 2];
        const float h3 = g[8 + n*4 + 3];
        const float hp = g[4 + n];
        float4 u;
        u.x = h0*s0.x + h1*s1.x + h2*s2.x + h3*s3.x + hp*ov.x;
        u.y = h0*s0.y + h1*s1.y + h2*s2.y + h3*s3.y + hp*ov.y;
        u.z = h0*s0.z + h1*s1.z + h2*s2.z + h3*s3.z + hp*ov.z;
        u.w = h0*s0.w + h1*s1.w + h2*s2.w + h3*s3.w + hp*ov.w;
        up[n * 256 + tid] = u;
    }
}

// ---------------------------------------------------------------------------
extern "C" void kernel_launch(void* const* d_in, const int* in_sizes, int n_in,
                              void* d_out, int out_size)
{
    const float* stream = (const float*)d_in[0];
    const float* outv   = (const float*)d_in[1];
    const float* w_pre  = (const float*)d_in[2];
    const float* w_post = (const float*)d_in[3];
    const float* w_res  = (const float*)d_in[4];
    const float* b_pre  = (const float*)d_in[5];
    const float* b_post = (const float*)d_in[6];
    const float* b_res  = (const float*)d_in[7];
    const float* a_pre  = (const float*)d_in[8];
    const float* a_post = (const float*)d_in[9];
    const float* a_res  = (const float*)d_in[10];

    float* xin = (float*)d_out;                      // (B,T,C)
    float* upd = xin + (size_t)BT * CDIM;            // (B,T,N,C)

    k1_gates<<<BT / TM, NT1>>>(stream, w_pre, w_post, w_res,
                               b_pre, b_post, b_res,
                               a_pre, a_post, a_res);
    k2_combine<<<BT, 256>>>(stream, outv, xin, upd);
}